// round 4
// baseline (speedup 1.0000x reference)
#include <cuda_runtime.h>

#define TB        32
#define NTHREADS  512
#define OBS       464
#define SROW      260      // padded activation row stride (floats)

typedef unsigned long long ull;

// ---------- f32x2 helpers ----------
__device__ __forceinline__ ull pk2(float lo, float hi) {
    ull r; asm("mov.b64 %0, {%1, %2};" : "=l"(r) : "f"(lo), "f"(hi)); return r;
}
__device__ __forceinline__ float2 upk2(ull v) {
    float2 f; asm("mov.b64 {%0, %1}, %2;" : "=f"(f.x), "=f"(f.y) : "l"(v)); return f;
}
__device__ __forceinline__ void fma2(ull& d, ull a, ull b) {
    asm("fma.rn.f32x2 %0, %1, %2, %0;" : "+l"(d) : "l"(a), "l"(b));
}

// tanh(x) = 1 - 2/(exp(2x)+1): ~1e-6 rel err (ex2 + rcp on MUFU pipe)
__device__ __forceinline__ float ftanh(float x) {
    float e = __expf(x + x);
    return 1.0f - __fdividef(2.0f, e + 1.0f);
}

// ---------- cp.async ----------
__device__ __forceinline__ void cpa16(void* s, const void* g) {
    unsigned sa = (unsigned)__cvta_generic_to_shared(s);
    asm volatile("cp.async.cg.shared.global [%0], [%1], 16;" :: "r"(sa), "l"(g));
}
#define CPCOMMIT() asm volatile("cp.async.commit_group;")
#define CPWAIT0()  asm volatile("cp.async.wait_group 0;")

// prefetch one 16x256 chunk (4096 floats) of W into smem (512 threads)
__device__ __forceinline__ void pf_half(float* dst, const float* src, int tid) {
#pragma unroll
    for (int i = 0; i < 2; ++i)
        cpa16(dst + (i * 512 + tid) * 4, src + (i * 512 + tid) * 4);
}

// ---------- acc helpers: 2 rows x 4 f32x2 pairs (8 cols) ----------
__device__ __forceinline__ void acc_zero(ull acc[2][4]) {
#pragma unroll
    for (int r = 0; r < 2; ++r)
#pragma unroll
        for (int p = 0; p < 4; ++p) acc[r][p] = 0ULL;
}
__device__ __forceinline__ void acc_bias(ull acc[2][4], const float* __restrict__ b, int gcol) {
    float4 b0 = *reinterpret_cast<const float4*>(b + gcol);
    float4 b1 = *reinterpret_cast<const float4*>(b + gcol + 4);
    ull p0 = pk2(b0.x, b0.y), p1 = pk2(b0.z, b0.w);
    ull p2 = pk2(b1.x, b1.y), p3 = pk2(b1.z, b1.w);
#pragma unroll
    for (int r = 0; r < 2; ++r) {
        acc[r][0] = p0; acc[r][1] = p1; acc[r][2] = p2; acc[r][3] = p3;
    }
}
__device__ __forceinline__ void epi_raw(float* dst, int dstride, int grow0, int gcol,
                                        const ull acc[2][4]) {
#pragma unroll
    for (int r = 0; r < 2; ++r) {
        float* p = dst + (grow0 + r) * dstride + gcol;
        float2 t0 = upk2(acc[r][0]), t1 = upk2(acc[r][1]);
        float2 t2 = upk2(acc[r][2]), t3 = upk2(acc[r][3]);
        *reinterpret_cast<float4*>(p)     = make_float4(t0.x, t0.y, t1.x, t1.y);
        *reinterpret_cast<float4*>(p + 4) = make_float4(t2.x, t2.y, t3.x, t3.y);
    }
}
__device__ __forceinline__ void epi_tanh(float* dst, int dstride, int grow0, int gcol,
                                         const ull acc[2][4]) {
#pragma unroll
    for (int r = 0; r < 2; ++r) {
        float* p = dst + (grow0 + r) * dstride + gcol;
        float2 t0 = upk2(acc[r][0]), t1 = upk2(acc[r][1]);
        float2 t2 = upk2(acc[r][2]), t3 = upk2(acc[r][3]);
        *reinterpret_cast<float4*>(p) =
            make_float4(ftanh(t0.x), ftanh(t0.y), ftanh(t1.x), ftanh(t1.y));
        *reinterpret_cast<float4*>(p + 4) =
            make_float4(ftanh(t2.x), ftanh(t2.y), ftanh(t3.x), ftanh(t3.y));
    }
}

// ---------- GEMM: [32 x 256] += A[32 x 16*nchunk] * W[16*nchunk x 256] ----------
// 16 warps; warp tile 8 rows x 64 cols; thread tile 2x8.
// W streamed via cp.async double-buffered 16-row chunks, ONE sync per chunk.
__device__ __forceinline__ void gemm_tiles(
    ull acc[2][4], const float* __restrict__ sA, int astride, int grow0, int gcol,
    const float* __restrict__ W, int nchunk, float* __restrict__ sW, int tid)
{
    pf_half(sW, W, tid);
    CPCOMMIT();
    for (int c = 0; c < nchunk; ++c) {
        CPWAIT0();               // chunk c (this thread's slice) arrived
        __syncthreads();         // chunk c visible to all; compute c-1 done everywhere
        if (c + 1 < nchunk) {
            pf_half(sW + ((c + 1) & 1) * 4096, W + (c + 1) * 4096, tid);
            CPCOMMIT();
        }
        const float* buf = sW + (c & 1) * 4096;
        const float* Ab = sA + grow0 * astride + c * 16;
#pragma unroll
        for (int k4 = 0; k4 < 16; k4 += 4) {
            float a0[4], a1[4];
            *reinterpret_cast<float4*>(a0) =
                *reinterpret_cast<const float4*>(Ab + k4);
            *reinterpret_cast<float4*>(a1) =
                *reinterpret_cast<const float4*>(Ab + astride + k4);
#pragma unroll
            for (int kk = 0; kk < 4; ++kk) {
                const ulonglong2* wr =
                    reinterpret_cast<const ulonglong2*>(buf + (k4 + kk) * 256 + gcol);
                ulonglong2 w01 = wr[0], w23 = wr[1];
                ull x0 = pk2(a0[kk], a0[kk]);
                ull x1 = pk2(a1[kk], a1[kk]);
                fma2(acc[0][0], x0, w01.x); fma2(acc[0][1], x0, w01.y);
                fma2(acc[0][2], x0, w23.x); fma2(acc[0][3], x0, w23.y);
                fma2(acc[1][0], x1, w01.x); fma2(acc[1][1], x1, w01.y);
                fma2(acc[1][2], x1, w23.x); fma2(acc[1][3], x1, w23.y);
            }
        }
    }
}

// ---------- attention with online softmax (warp owns the row) ----------
template<int N, int F>
__device__ __forceinline__ void attend_group(
    const float* __restrict__ feats,           // smem: N*F features of this row
    const float* __restrict__ Wg,              // smem: F x 256
    const float* __restrict__ bg,              // smem: 256
    float* __restrict__ qv,                    // smem: q in, vi out (256-float slot)
    int c0, int c1)
{
    float4 q0 = *reinterpret_cast<const float4*>(qv + c0);
    float4 q1 = *reinterpret_cast<const float4*>(qv + c1);
    ulonglong2 bb01 = *reinterpret_cast<const ulonglong2*>(bg + c0);
    ulonglong2 bb23 = *reinterpret_cast<const ulonglong2*>(bg + c1);

    float m = -3.0e38f, s = 0.0f;
    float v[8];
#pragma unroll
    for (int i = 0; i < 8; ++i) v[i] = 0.0f;

#pragma unroll 1
    for (int n = 0; n < N; ++n) {
        const float* fp = feats + n * F;
        ull a0 = bb01.x, a1 = bb01.y, a2 = bb23.x, a3 = bb23.y;
#pragma unroll
        for (int j = 0; j < F; ++j) {
            float fv = fp[j];
            ull f2 = pk2(fv, fv);
            ulonglong2 w01 = *reinterpret_cast<const ulonglong2*>(Wg + j * 256 + c0);
            ulonglong2 w23 = *reinterpret_cast<const ulonglong2*>(Wg + j * 256 + c1);
            fma2(a0, f2, w01.x); fma2(a1, f2, w01.y);
            fma2(a2, f2, w23.x); fma2(a3, f2, w23.y);
        }
        float e[8];
        float2 t;
        t = upk2(a0); e[0] = ftanh(t.x); e[1] = ftanh(t.y);
        t = upk2(a1); e[2] = ftanh(t.x); e[3] = ftanh(t.y);
        t = upk2(a2); e[4] = ftanh(t.x); e[5] = ftanh(t.y);
        t = upk2(a3); e[6] = ftanh(t.x); e[7] = ftanh(t.y);

        float beta = q0.x * e[0] + q0.y * e[1] + q0.z * e[2] + q0.w * e[3]
                   + q1.x * e[4] + q1.y * e[5] + q1.z * e[6] + q1.w * e[7];
#pragma unroll
        for (int sh = 16; sh > 0; sh >>= 1) beta += __shfl_xor_sync(0xffffffffu, beta, sh);

        float mn = fmaxf(m, beta);
        float scale = __expf(m - mn);      // 0 on first iter
        float wgt   = __expf(beta - mn);
        s = s * scale + wgt;
#pragma unroll
        for (int i = 0; i < 8; ++i) v[i] = v[i] * scale + wgt * e[i];
        m = mn;
    }
    float inv = __fdividef(1.0f, s);
    *reinterpret_cast<float4*>(qv + c0) =
        make_float4(v[0] * inv, v[1] * inv, v[2] * inv, v[3] * inv);
    *reinterpret_cast<float4*>(qv + c1) =
        make_float4(v[4] * inv, v[5] * inv, v[6] * inv, v[7] * inv);
}

// Shared memory layout (floats):
//  sIn  @ 0     : 32*464 = 14848  (inputs; reused as h, stride 260, after attention)
//  sEmb @ 14848 : 32*260 =  8320  (emb_self -> gi)
//  sQ   @ 23168 : 3*8320 = 24960  (q_other|q_box|q_ramp -> vi_*)
//  sW   @ 48128 : 9728            (GEMM double buffer 2x4096 / entity weights+biases)
// total 57856 floats = 231424 bytes
#define SMEM_FLOATS 57856
#define SMEM_BYTES  (SMEM_FLOATS * 4)

__global__ void __launch_bounds__(NTHREADS, 1)
obs_encoder_kernel(
    const float* __restrict__ gIn,
    const float* __restrict__ W_self,  const float* __restrict__ b_self,
    const float* __restrict__ W_other, const float* __restrict__ b_other,
    const float* __restrict__ W_box,   const float* __restrict__ b_box,
    const float* __restrict__ W_ramp,  const float* __restrict__ b_ramp,
    const float* __restrict__ corr_other, const float* __restrict__ corr_box,
    const float* __restrict__ corr_ramp,
    const float* __restrict__ W_fc, const float* __restrict__ b_fc,
    const float* __restrict__ W_e1, const float* __restrict__ b_e1,
    const float* __restrict__ W_e2, const float* __restrict__ b_e2,
    float* __restrict__ out)
{
    extern __shared__ float sm[];
    float* sIn  = sm;
    float* sEmb = sm + 14848;
    float* sQ   = sm + 23168;
    float* sW   = sm + 48128;

    const int tid  = threadIdx.x;
    const int lane = tid & 31;
    const int w    = tid >> 5;                 // 0..15
    // GEMM mapping: warp tile 8 rows x 64 cols; thread tile 2x8
    const int lr = lane >> 3, lc = lane & 7;
    const int grow0 = (w & 3) * 8 + lr * 2;    // 2 consecutive block-local rows
    const int gcol  = (w >> 2) * 64 + lc * 8;  // 8 consecutive cols
    // attention mapping: warp owns rows w*2, w*2+1; lane owns cols c0,c1
    const int c0 = lane * 4, c1 = c0 + 128;
    const size_t row0 = (size_t)blockIdx.x * TB;

    // ---- phase 0: stage 32 input rows (14848 floats = 7424 float2) ----
    {
        const float2* src = reinterpret_cast<const float2*>(gIn + row0 * OBS);
        float2* dst = reinterpret_cast<float2*>(sIn);
#pragma unroll
        for (int i = 0; i < 14; ++i) dst[i * 512 + tid] = src[i * 512 + tid];
        if (tid < 256) dst[7168 + tid] = src[7168 + tid];
    }
    __syncthreads();

    // ---- phase 1: emb_self = tanh(self_in @ W_self + b_self), K=10 ----
    {
        ull acc[2][4];
        acc_bias(acc, b_self, gcol);
#pragma unroll
        for (int k = 0; k < 10; ++k) {
            const ulonglong2* wr =
                reinterpret_cast<const ulonglong2*>(W_self + k * 256 + gcol);
            ulonglong2 w01 = wr[0], w23 = wr[1];
#pragma unroll
            for (int r = 0; r < 2; ++r) {
                float a = sIn[(grow0 + r) * OBS + k];
                ull a2 = pk2(a, a);
                fma2(acc[r][0], a2, w01.x); fma2(acc[r][1], a2, w01.y);
                fma2(acc[r][2], a2, w23.x); fma2(acc[r][3], a2, w23.y);
            }
        }
        epi_tanh(sEmb, SROW, grow0, gcol, acc);
    }
    // gemm_tiles' first internal sync orders the sEmb stores before first compute

    // ---- phase 2: q_g = emb_self @ corr_g, gi = tanh(emb_self @ W_fc + b_fc) ----
    {
        ull acc[2][4];
        acc_zero(acc);
        gemm_tiles(acc, sEmb, SROW, grow0, gcol, corr_other, 16, sW, tid);
        epi_raw(sQ, SROW, grow0, gcol, acc);

        acc_zero(acc);
        gemm_tiles(acc, sEmb, SROW, grow0, gcol, corr_box, 16, sW, tid);
        epi_raw(sQ + 8320, SROW, grow0, gcol, acc);

        acc_zero(acc);
        gemm_tiles(acc, sEmb, SROW, grow0, gcol, corr_ramp, 16, sW, tid);
        epi_raw(sQ + 16640, SROW, grow0, gcol, acc);

        acc_bias(acc, b_fc, gcol);
        gemm_tiles(acc, sEmb, SROW, grow0, gcol, W_fc, 16, sW, tid);
        __syncthreads();   // all A-reads of emb_self done before overwrite with gi
        epi_tanh(sEmb, SROW, grow0, gcol, acc);
    }

    // ---- phase 3: attention pools (warp-private rows, online softmax) ----
    {
        __syncthreads();   // gi + q stores visible; sW free for entity weights
        for (int i = tid; i < 2560; i += NTHREADS) sW[i]        = W_other[i];
        for (int i = tid; i < 3328; i += NTHREADS) sW[2816 + i] = W_box[i];
        for (int i = tid; i < 3072; i += NTHREADS) sW[6400 + i] = W_ramp[i];
        if (tid < 256) {
            sW[2560 + tid] = b_other[tid];
            sW[6144 + tid] = b_box[tid];
            sW[9472 + tid] = b_ramp[tid];
        }
        __syncthreads();

#pragma unroll 1
        for (int r = 0; r < 2; ++r) {
            const int row = w * 2 + r;
            const float* inrow = sIn + row * OBS;
            attend_group<15, 10>(inrow + 10,  sW,        sW + 2560, sQ + row * SROW,         c0, c1);
            attend_group<16, 13>(inrow + 160, sW + 2816, sW + 6144, sQ + 8320 + row * SROW,  c0, c1);
            attend_group<8, 12>( inrow + 368, sW + 6400, sW + 9472, sQ + 16640 + row * SROW, c0, c1);
        }
        __syncthreads();   // attention done before sW reuse + vi reads by other warps
    }

    // ---- phase 4: h = tanh(cat @ W_e1 + b_e1), cat = [gi | vi_o | vi_b | vi_r] ----
    {
        ull acc[2][4];
        acc_bias(acc, b_e1, gcol);
        gemm_tiles(acc, sEmb,       SROW, grow0, gcol, W_e1,          16, sW, tid);
        gemm_tiles(acc, sQ,         SROW, grow0, gcol, W_e1 + 65536,  16, sW, tid);
        gemm_tiles(acc, sQ + 8320,  SROW, grow0, gcol, W_e1 + 131072, 16, sW, tid);
        gemm_tiles(acc, sQ + 16640, SROW, grow0, gcol, W_e1 + 196608, 16, sW, tid);
        // sIn (inputs) is dead now; reuse as h (stride 260).
        epi_tanh(sIn, SROW, grow0, gcol, acc);
    }

    // ---- phase 5: out = tanh(h @ W_e2 + b_e2) ----
    {
        ull acc[2][4];
        acc_bias(acc, b_e2, gcol);
        gemm_tiles(acc, sIn, SROW, grow0, gcol, W_e2, 16, sW, tid);  // internal sync orders h
#pragma unroll
        for (int r = 0; r < 2; ++r) {
            float* p = out + (row0 + grow0 + r) * 256 + gcol;
            float2 t0 = upk2(acc[r][0]), t1 = upk2(acc[r][1]);
            float2 t2 = upk2(acc[r][2]), t3 = upk2(acc[r][3]);
            *reinterpret_cast<float4*>(p) =
                make_float4(ftanh(t0.x), ftanh(t0.y), ftanh(t1.x), ftanh(t1.y));
            *reinterpret_cast<float4*>(p + 4) =
                make_float4(ftanh(t2.x), ftanh(t2.y), ftanh(t3.x), ftanh(t3.y));
        }
    }
}

extern "C" void kernel_launch(void* const* d_in, const int* in_sizes, int n_in,
                              void* d_out, int out_size) {
    const float* inputs     = (const float*)d_in[0];
    const float* W_self     = (const float*)d_in[1];
    const float* b_self     = (const float*)d_in[2];
    const float* W_other    = (const float*)d_in[3];
    const float* b_other    = (const float*)d_in[4];
    const float* W_box      = (const float*)d_in[5];
    const float* b_box      = (const float*)d_in[6];
    const float* W_ramp     = (const float*)d_in[7];
    const float* b_ramp     = (const float*)d_in[8];
    const float* corr_other = (const float*)d_in[9];
    const float* corr_box   = (const float*)d_in[10];
    const float* corr_ramp  = (const float*)d_in[11];
    const float* W_fc       = (const float*)d_in[12];
    const float* b_fc       = (const float*)d_in[13];
    const float* W_e1       = (const float*)d_in[14];
    const float* b_e1       = (const float*)d_in[15];
    const float* W_e2       = (const float*)d_in[16];
    const float* b_e2       = (const float*)d_in[17];
    float* out = (float*)d_out;

    const int B = in_sizes[0] / OBS;       // 32768
    const int nblocks = B / TB;            // 1024

    cudaFuncSetAttribute(obs_encoder_kernel,
                         cudaFuncAttributeMaxDynamicSharedMemorySize, SMEM_BYTES);

    obs_encoder_kernel<<<nblocks, NTHREADS, SMEM_BYTES>>>(
        inputs, W_self, b_self, W_other, b_other, W_box, b_box, W_ramp, b_ramp,
        corr_other, corr_box, corr_ramp, W_fc, b_fc, W_e1, b_e1, W_e2, b_e2, out);
}

// round 5
// speedup vs baseline: 1.8757x; 1.8757x over previous
#include <cuda_runtime.h>

#define TB        32
#define NTHREADS  256
#define OBS       464
#define SROW      257     // odd stride: lane-indexed rows hit distinct banks

typedef unsigned long long ull;

// ---------- f32x2 helpers ----------
__device__ __forceinline__ ull pk2(float lo, float hi) {
    ull r; asm("mov.b64 %0, {%1, %2};" : "=l"(r) : "f"(lo), "f"(hi)); return r;
}
__device__ __forceinline__ float2 upk2(ull v) {
    float2 f; asm("mov.b64 {%0, %1}, %2;" : "=f"(f.x), "=f"(f.y) : "l"(v)); return f;
}
__device__ __forceinline__ void fma2(ull& d, ull a, ull b) {
    asm("fma.rn.f32x2 %0, %1, %2, %0;" : "+l"(d) : "l"(a), "l"(b));
}

// tanh(x) = 1 - 2/(exp(2x)+1): ~1e-6 rel err
__device__ __forceinline__ float ftanh(float x) {
    float e = __expf(x + x);
    return 1.0f - __fdividef(2.0f, e + 1.0f);
}

// ---------- cp.async ----------
__device__ __forceinline__ void cpa16(void* s, const void* g) {
    unsigned sa = (unsigned)__cvta_generic_to_shared(s);
    asm volatile("cp.async.cg.shared.global [%0], [%1], 16;" :: "r"(sa), "l"(g));
}
#define CPCOMMIT() asm volatile("cp.async.commit_group;")
#define CPWAIT0()  asm volatile("cp.async.wait_group 0;")

// prefetch one 16x256 W chunk (4096 floats) into smem
__device__ __forceinline__ void pf_chunk(float* dst, const float* src, int tid) {
#pragma unroll
    for (int i = 0; i < 4; ++i)
        cpa16(dst + (i * 256 + tid) * 4, src + (i * 256 + tid) * 4);
}

// ---------- acc helpers: 1 row x 32 cols = 16 f32x2 ----------
__device__ __forceinline__ void acc_zero(ull acc[16]) {
#pragma unroll
    for (int i = 0; i < 16; ++i) acc[i] = 0ULL;
}
__device__ __forceinline__ void acc_bias(ull acc[16], const float* __restrict__ b, int gcolW) {
    const ulonglong2* p = reinterpret_cast<const ulonglong2*>(b + gcolW);
#pragma unroll
    for (int i = 0; i < 8; ++i) {
        ulonglong2 t = p[i];
        acc[2 * i] = t.x; acc[2 * i + 1] = t.y;
    }
}
// d = row base + gcolW; scalar stores, lane-distinct banks (stride 257)
__device__ __forceinline__ void epi_raw(float* d, const ull acc[16]) {
#pragma unroll
    for (int i = 0; i < 16; ++i) {
        float2 t = upk2(acc[i]);
        d[2 * i] = t.x; d[2 * i + 1] = t.y;
    }
}
__device__ __forceinline__ void epi_tanh(float* d, const ull acc[16]) {
#pragma unroll
    for (int i = 0; i < 16; ++i) {
        float2 t = upk2(acc[i]);
        d[2 * i] = ftanh(t.x); d[2 * i + 1] = ftanh(t.y);
    }
}

// ---------- GEMM: [32 x 256] += A[32 x 256] * W[256 x 256] ----------
// Warp w owns cols [32w, 32w+32); lane owns row = lane.
// W read as broadcast LDS.128 (all lanes same address, N=1 free).
// A read as lane-per-row LDS.32 from stride-257 smem (conflict-free).
__device__ __forceinline__ void gemm256(
    ull acc[16], const float* __restrict__ sA,   // pre-offset: sEmb + lane*257
    const float* __restrict__ W,                  // global [256 x 256]
    float* __restrict__ sW, int tid, int gcolW)
{
    pf_chunk(sW, W, tid);
    CPCOMMIT();
#pragma unroll 1
    for (int c = 0; c < 16; ++c) {
        CPWAIT0();               // own slice of chunk c arrived
        __syncthreads();         // chunk c visible to all; compute c-1 done everywhere
        if (c + 1 < 16) {
            pf_chunk(sW + ((c + 1) & 1) * 4096, W + (c + 1) * 4096, tid);
            CPCOMMIT();
        }
        const float* buf = sW + (c & 1) * 4096 + gcolW;
        const float* a = sA + c * 16;
#pragma unroll
        for (int k = 0; k < 16; ++k) {
            float av = a[k];
            ull a2 = pk2(av, av);
            const ulonglong2* wp = reinterpret_cast<const ulonglong2*>(buf + k * 256);
            ulonglong2 w0 = wp[0], w1 = wp[1], w2 = wp[2], w3 = wp[3];
            fma2(acc[0], a2, w0.x);  fma2(acc[1], a2, w0.y);
            fma2(acc[2], a2, w1.x);  fma2(acc[3], a2, w1.y);
            fma2(acc[4], a2, w2.x);  fma2(acc[5], a2, w2.y);
            fma2(acc[6], a2, w3.x);  fma2(acc[7], a2, w3.y);
            ulonglong2 w4 = wp[4], w5 = wp[5], w6 = wp[6], w7 = wp[7];
            fma2(acc[8],  a2, w4.x); fma2(acc[9],  a2, w4.y);
            fma2(acc[10], a2, w5.x); fma2(acc[11], a2, w5.y);
            fma2(acc[12], a2, w6.x); fma2(acc[13], a2, w6.y);
            fma2(acc[14], a2, w7.x); fma2(acc[15], a2, w7.y);
        }
    }
}

// ---------- attention, 4 rows batched per warp, online softmax ----------
// Entity W column slice loaded ONCE per j and reused across the warp's 4 rows.
template<int N, int F>
__device__ __forceinline__ void attend4(
    const float* __restrict__ sInB,   // sIn + r0*OBS
    int featoff,
    const float* __restrict__ Wg,     // smem F x 256
    const float* __restrict__ bg,     // smem 256
    float* __restrict__ sQg,          // sQ group + r0*SROW : q in, vi out
    int c0, int c1)
{
    float4 bA = *reinterpret_cast<const float4*>(bg + c0);
    float4 bB = *reinterpret_cast<const float4*>(bg + c1);
    ull bb0 = pk2(bA.x, bA.y), bb1 = pk2(bA.z, bA.w);
    ull bb2 = pk2(bB.x, bB.y), bb3 = pk2(bB.z, bB.w);

    float q[4][8];
#pragma unroll
    for (int r = 0; r < 4; ++r) {
#pragma unroll
        for (int i = 0; i < 4; ++i) {
            q[r][i]     = sQg[r * SROW + c0 + i];
            q[r][4 + i] = sQg[r * SROW + c1 + i];
        }
    }
    float m[4], s[4], v[4][8];
#pragma unroll
    for (int r = 0; r < 4; ++r) {
        m[r] = -3.0e38f; s[r] = 0.0f;
#pragma unroll
        for (int i = 0; i < 8; ++i) v[r][i] = 0.0f;
    }

#pragma unroll 1
    for (int n = 0; n < N; ++n) {
        ull e0[4], e1[4], e2[4], e3[4];
#pragma unroll
        for (int r = 0; r < 4; ++r) { e0[r] = bb0; e1[r] = bb1; e2[r] = bb2; e3[r] = bb3; }
        const float* f0 = sInB + featoff + n * F;
#pragma unroll
        for (int j = 0; j < F; ++j) {
            ulonglong2 wA = *reinterpret_cast<const ulonglong2*>(Wg + j * 256 + c0);
            ulonglong2 wB = *reinterpret_cast<const ulonglong2*>(Wg + j * 256 + c1);
#pragma unroll
            for (int r = 0; r < 4; ++r) {
                float fv = f0[r * OBS + j];       // broadcast (all lanes same addr)
                ull f2 = pk2(fv, fv);
                fma2(e0[r], f2, wA.x); fma2(e1[r], f2, wA.y);
                fma2(e2[r], f2, wB.x); fma2(e3[r], f2, wB.y);
            }
        }
#pragma unroll
        for (int r = 0; r < 4; ++r) {
            float ee[8];
            float2 t;
            t = upk2(e0[r]); ee[0] = ftanh(t.x); ee[1] = ftanh(t.y);
            t = upk2(e1[r]); ee[2] = ftanh(t.x); ee[3] = ftanh(t.y);
            t = upk2(e2[r]); ee[4] = ftanh(t.x); ee[5] = ftanh(t.y);
            t = upk2(e3[r]); ee[6] = ftanh(t.x); ee[7] = ftanh(t.y);

            float beta = q[r][0] * ee[0] + q[r][1] * ee[1] + q[r][2] * ee[2] + q[r][3] * ee[3]
                       + q[r][4] * ee[4] + q[r][5] * ee[5] + q[r][6] * ee[6] + q[r][7] * ee[7];
#pragma unroll
            for (int sh = 16; sh > 0; sh >>= 1) beta += __shfl_xor_sync(0xffffffffu, beta, sh);

            float mn = fmaxf(m[r], beta);
            float sc = __expf(m[r] - mn);         // 0 on first entity
            float wt = __expf(beta - mn);
            s[r] = s[r] * sc + wt;
#pragma unroll
            for (int i = 0; i < 8; ++i) v[r][i] = v[r][i] * sc + wt * ee[i];
            m[r] = mn;
        }
    }
#pragma unroll
    for (int r = 0; r < 4; ++r) {
        float inv = __fdividef(1.0f, s[r]);
#pragma unroll
        for (int i = 0; i < 4; ++i) {
            sQg[r * SROW + c0 + i] = v[r][i] * inv;
            sQg[r * SROW + c1 + i] = v[r][4 + i] * inv;
        }
    }
}

// Shared memory layout (floats):
//  sIn  @ 0     : 32*464 = 14848   (staged inputs, stride 464)
//  sEmb @ 14848 : 32*257 =  8224   (emb_self -> gi -> h)
//  sQ   @ 23072 : 3*8224 = 24672   (q_* -> vi_*; sQ0 reused as out staging)
//  sW   @ 47744 : 9728             (GEMM double buffer 2x4096 / entity weights)
// total 57472 floats = 229888 bytes
#define SMEM_FLOATS 57472
#define SMEM_BYTES  (SMEM_FLOATS * 4)

__global__ void __launch_bounds__(NTHREADS, 1)
obs_encoder_kernel(
    const float* __restrict__ gIn,
    const float* __restrict__ W_self,  const float* __restrict__ b_self,
    const float* __restrict__ W_other, const float* __restrict__ b_other,
    const float* __restrict__ W_box,   const float* __restrict__ b_box,
    const float* __restrict__ W_ramp,  const float* __restrict__ b_ramp,
    const float* __restrict__ corr_other, const float* __restrict__ corr_box,
    const float* __restrict__ corr_ramp,
    const float* __restrict__ W_fc, const float* __restrict__ b_fc,
    const float* __restrict__ W_e1, const float* __restrict__ b_e1,
    const float* __restrict__ W_e2, const float* __restrict__ b_e2,
    float* __restrict__ out)
{
    extern __shared__ float sm[];
    float* sIn  = sm;
    float* sEmb = sm + 14848;
    float* sQ0  = sm + 23072;
    float* sQ1  = sQ0 + 8224;
    float* sQ2  = sQ1 + 8224;
    float* sW   = sm + 47744;

    const int tid  = threadIdx.x;
    const int lane = tid & 31;
    const int w    = tid >> 5;              // 0..7
    const int gcolW = w * 32;               // GEMM: warp's 32-col range; lane's row = lane
    // attention mapping: warp owns rows 4w..4w+3; lane owns cols c0, c1
    const int c0 = lane * 4, c1 = c0 + 128;
    const int r0 = w * 4;
    const size_t row0 = (size_t)blockIdx.x * TB;

    // ---- phase 0: stage 32 input rows (14848 floats = 3712 float4) ----
    {
        const float4* src = reinterpret_cast<const float4*>(gIn + row0 * OBS);
        float4* dst = reinterpret_cast<float4*>(sIn);
#pragma unroll
        for (int i = 0; i < 15; ++i) {
            int idx = i * 256 + tid;
            if (idx < 3712) dst[idx] = src[idx];
        }
    }
    __syncthreads();

    // ---- phase 1: emb_self = tanh(self_in @ W_self + b_self), K=10 ----
    {
        ull acc[16];
        acc_bias(acc, b_self, gcolW);
#pragma unroll
        for (int k = 0; k < 10; ++k) {
            float av = sIn[lane * OBS + k];
            ull a2 = pk2(av, av);
            const ulonglong2* wp =
                reinterpret_cast<const ulonglong2*>(W_self + k * 256 + gcolW);
#pragma unroll
            for (int i = 0; i < 8; ++i) {
                ulonglong2 ww = wp[i];
                fma2(acc[2 * i], a2, ww.x); fma2(acc[2 * i + 1], a2, ww.y);
            }
        }
        epi_tanh(sEmb + lane * SROW + gcolW, acc);
    }
    // gemm256's first internal sync orders these stores before first A-read

    // ---- phase 2: q_g = emb_self @ corr_g (raw), gi = tanh(emb_self @ W_fc + b) ----
    {
        ull acc[16];
        acc_zero(acc);
        gemm256(acc, sEmb + lane * SROW, corr_other, sW, tid, gcolW);
        epi_raw(sQ0 + lane * SROW + gcolW, acc);

        acc_zero(acc);
        gemm256(acc, sEmb + lane * SROW, corr_box, sW, tid, gcolW);
        epi_raw(sQ1 + lane * SROW + gcolW, acc);

        acc_zero(acc);
        gemm256(acc, sEmb + lane * SROW, corr_ramp, sW, tid, gcolW);
        epi_raw(sQ2 + lane * SROW + gcolW, acc);

        acc_bias(acc, b_fc, gcolW);
        gemm256(acc, sEmb + lane * SROW, W_fc, sW, tid, gcolW);
        __syncthreads();   // all A-reads of emb_self done before gi overwrites it
        epi_tanh(sEmb + lane * SROW + gcolW, acc);
    }

    // ---- phase 3: attention pools ----
    {
        __syncthreads();   // gi epi + last GEMM done; sW free; q stores visible
        for (int i = tid; i < 2560; i += NTHREADS) sW[i]        = W_other[i];
        for (int i = tid; i < 3328; i += NTHREADS) sW[2816 + i] = W_box[i];
        for (int i = tid; i < 3072; i += NTHREADS) sW[6400 + i] = W_ramp[i];
        sW[2560 + tid] = b_other[tid];
        sW[6144 + tid] = b_box[tid];
        sW[9472 + tid] = b_ramp[tid];
        __syncthreads();

        const float* sInB = sIn + r0 * OBS;
        attend4<15, 10>(sInB, 10,  sW,        sW + 2560, sQ0 + r0 * SROW, c0, c1);
        attend4<16, 13>(sInB, 160, sW + 2816, sW + 6144, sQ1 + r0 * SROW, c0, c1);
        attend4<8, 12>( sInB, 368, sW + 6400, sW + 9472, sQ2 + r0 * SROW, c0, c1);
        __syncthreads();   // vi visible to all; sW free for GEMM chunks
    }

    // ---- phase 4: h = tanh(cat @ W_e1 + b_e1), cat = [gi | vi_o | vi_b | vi_r] ----
    {
        ull acc[16];
        acc_bias(acc, b_e1, gcolW);
        gemm256(acc, sEmb + lane * SROW, W_e1,          sW, tid, gcolW);
        gemm256(acc, sQ0  + lane * SROW, W_e1 + 65536,  sW, tid, gcolW);
        gemm256(acc, sQ1  + lane * SROW, W_e1 + 131072, sW, tid, gcolW);
        gemm256(acc, sQ2  + lane * SROW, W_e1 + 196608, sW, tid, gcolW);
        __syncthreads();   // all gi reads long done; all warps past last chunk
        epi_tanh(sEmb + lane * SROW + gcolW, acc);   // h -> sEmb
    }

    // ---- phase 5: out = tanh(h @ W_e2 + b_e2) ----
    {
        ull acc[16];
        acc_bias(acc, b_e2, gcolW);
        gemm256(acc, sEmb + lane * SROW, W_e2, sW, tid, gcolW);  // internal sync orders h
        epi_tanh(sQ0 + lane * SROW + gcolW, acc);   // stage result (sQ0 dead)
        __syncthreads();
        // coalesced writeback: one full row per iteration
        float* gout = out + row0 * 256;
#pragma unroll 4
        for (int i = 0; i < 32; ++i)
            gout[i * 256 + tid] = sQ0[i * SROW + tid];
    }
}

extern "C" void kernel_launch(void* const* d_in, const int* in_sizes, int n_in,
                              void* d_out, int out_size) {
    const float* inputs     = (const float*)d_in[0];
    const float* W_self     = (const float*)d_in[1];
    const float* b_self     = (const float*)d_in[2];
    const float* W_other    = (const float*)d_in[3];
    const float* b_other    = (const float*)d_in[4];
    const float* W_box      = (const float*)d_in[5];
    const float* b_box      = (const float*)d_in[6];
    const float* W_ramp     = (const float*)d_in[7];
    const float* b_ramp     = (const float*)d_in[8];
    const float* corr_other = (const float*)d_in[9];
    const float* corr_box   = (const float*)d_in[10];
    const float* corr_ramp  = (const float*)d_in[11];
    const float* W_fc       = (const float*)d_in[12];
    const float* b_fc       = (const float*)d_in[13];
    const float* W_e1       = (const float*)d_in[14];
    const float* b_e1       = (const float*)d_in[15];
    const float* W_e2       = (const float*)d_in[16];
    const float* b_e2       = (const float*)d_in[17];
    float* out = (float*)d_out;

    const int B = in_sizes[0] / OBS;       // 32768
    const int nblocks = B / TB;            // 1024

    cudaFuncSetAttribute(obs_encoder_kernel,
                         cudaFuncAttributeMaxDynamicSharedMemorySize, SMEM_BYTES);

    obs_encoder_kernel<<<nblocks, NTHREADS, SMEM_BYTES>>>(
        inputs, W_self, b_self, W_other, b_other, W_box, b_box, W_ramp, b_ramp,
        corr_other, corr_box, corr_ramp, W_fc, b_fc, W_e1, b_e1, W_e2, b_e2, out);
}

// round 6
// speedup vs baseline: 2.1751x; 1.1596x over previous
#include <cuda_runtime.h>

#define TB        64
#define NTHREADS  256
#define OBS       464

typedef unsigned long long ull;

// ---------- f32x2 helpers ----------
__device__ __forceinline__ ull pk2(float lo, float hi) {
    ull r; asm("mov.b64 %0, {%1, %2};" : "=l"(r) : "f"(lo), "f"(hi)); return r;
}
__device__ __forceinline__ float2 upk2(ull v) {
    float2 f; asm("mov.b64 {%0, %1}, %2;" : "=f"(f.x), "=f"(f.y) : "l"(v)); return f;
}
__device__ __forceinline__ void fma2(ull& d, ull a, ull b) {
    asm("fma.rn.f32x2 %0, %1, %2, %0;" : "+l"(d) : "l"(a), "l"(b));
}

// tanh(x) = 1 - 2/(exp(2x)+1): ~1e-6 rel err
__device__ __forceinline__ float ftanh(float x) {
    float e = __expf(x + x);
    return 1.0f - __fdividef(2.0f, e + 1.0f);
}

// ---------- cp.async ----------
__device__ __forceinline__ void cpa16(void* s, const void* g) {
    unsigned sa = (unsigned)__cvta_generic_to_shared(s);
    asm volatile("cp.async.cg.shared.global [%0], [%1], 16;" :: "r"(sa), "l"(g));
}
#define CPCOMMIT() asm volatile("cp.async.commit_group;")
#define CPWAIT0()  asm volatile("cp.async.wait_group 0;")

// prefetch one 8x256 W chunk (2048 floats) into smem
__device__ __forceinline__ void pf8(float* dst, const float* src, int tid) {
    cpa16(dst + 4 * tid, src + 4 * tid);
    cpa16(dst + 1024 + 4 * tid, src + 1024 + 4 * tid);
}

// ---------- acc: 8 rows x 8 cols per lane = 32 f32x2 ----------
__device__ __forceinline__ void acc_zero(ull acc[32]) {
#pragma unroll
    for (int i = 0; i < 32; ++i) acc[i] = 0ULL;
}
__device__ __forceinline__ void acc_bias(ull acc[32], const float* __restrict__ b,
                                         int c0, int c1) {
    float4 b0 = *reinterpret_cast<const float4*>(b + c0);
    float4 b1 = *reinterpret_cast<const float4*>(b + c1);
    ull p0 = pk2(b0.x, b0.y), p1 = pk2(b0.z, b0.w);
    ull p2 = pk2(b1.x, b1.y), p3 = pk2(b1.z, b1.w);
#pragma unroll
    for (int r = 0; r < 8; ++r) {
        acc[r * 4 + 0] = p0; acc[r * 4 + 1] = p1;
        acc[r * 4 + 2] = p2; acc[r * 4 + 3] = p3;
    }
}
// dst = slot + r0*256 ; lane writes 8 rows x (c0..c0+3, c1..c1+3), aligned float4
__device__ __forceinline__ void epi_raw(float* dst, int c0, int c1, const ull acc[32]) {
#pragma unroll
    for (int r = 0; r < 8; ++r) {
        float2 t0 = upk2(acc[r * 4 + 0]), t1 = upk2(acc[r * 4 + 1]);
        float2 t2 = upk2(acc[r * 4 + 2]), t3 = upk2(acc[r * 4 + 3]);
        *reinterpret_cast<float4*>(dst + r * 256 + c0) = make_float4(t0.x, t0.y, t1.x, t1.y);
        *reinterpret_cast<float4*>(dst + r * 256 + c1) = make_float4(t2.x, t2.y, t3.x, t3.y);
    }
}
__device__ __forceinline__ void epi_tanh(float* dst, int c0, int c1, const ull acc[32]) {
#pragma unroll
    for (int r = 0; r < 8; ++r) {
        float2 t0 = upk2(acc[r * 4 + 0]), t1 = upk2(acc[r * 4 + 1]);
        float2 t2 = upk2(acc[r * 4 + 2]), t3 = upk2(acc[r * 4 + 3]);
        *reinterpret_cast<float4*>(dst + r * 256 + c0) =
            make_float4(ftanh(t0.x), ftanh(t0.y), ftanh(t1.x), ftanh(t1.y));
        *reinterpret_cast<float4*>(dst + r * 256 + c1) =
            make_float4(ftanh(t2.x), ftanh(t2.y), ftanh(t3.x), ftanh(t3.y));
    }
}
__device__ __forceinline__ void epi_add(float* dst, int c0, int c1, const ull acc[32]) {
#pragma unroll
    for (int r = 0; r < 8; ++r) {
        float4 oA = *reinterpret_cast<const float4*>(dst + r * 256 + c0);
        float4 oB = *reinterpret_cast<const float4*>(dst + r * 256 + c1);
        float2 t0 = upk2(acc[r * 4 + 0]), t1 = upk2(acc[r * 4 + 1]);
        float2 t2 = upk2(acc[r * 4 + 2]), t3 = upk2(acc[r * 4 + 3]);
        *reinterpret_cast<float4*>(dst + r * 256 + c0) =
            make_float4(oA.x + t0.x, oA.y + t0.y, oA.z + t1.x, oA.w + t1.y);
        *reinterpret_cast<float4*>(dst + r * 256 + c1) =
            make_float4(oB.x + t2.x, oB.y + t2.y, oB.z + t3.x, oB.w + t3.y);
    }
}
__device__ __forceinline__ void epi_add_tanh(float* dst, int c0, int c1, const ull acc[32]) {
#pragma unroll
    for (int r = 0; r < 8; ++r) {
        float4 oA = *reinterpret_cast<const float4*>(dst + r * 256 + c0);
        float4 oB = *reinterpret_cast<const float4*>(dst + r * 256 + c1);
        float2 t0 = upk2(acc[r * 4 + 0]), t1 = upk2(acc[r * 4 + 1]);
        float2 t2 = upk2(acc[r * 4 + 2]), t3 = upk2(acc[r * 4 + 3]);
        *reinterpret_cast<float4*>(dst + r * 256 + c0) =
            make_float4(ftanh(oA.x + t0.x), ftanh(oA.y + t0.y),
                        ftanh(oA.z + t1.x), ftanh(oA.w + t1.y));
        *reinterpret_cast<float4*>(dst + r * 256 + c1) =
            make_float4(ftanh(oB.x + t2.x), ftanh(oB.y + t2.y),
                        ftanh(oB.z + t3.x), ftanh(oB.w + t3.y));
    }
}

// ---------- GEMM: [64 x 256] += A[64 x 256] * W[256 x 256] ----------
// Warp = 8 rows x 256 cols (rows 8w..8w+8); lane = 8 rows x 8 cols (c0, c1).
// A read as broadcast float4 (same addr all lanes); W lane-distinct LDS.128.
// W streamed via cp.async double-buffered 8-row chunks, one sync per chunk.
__device__ __forceinline__ void gemm256(
    ull acc[32], const float* __restrict__ sA,   // slot + r0*256
    const float* __restrict__ W,
    float* __restrict__ sW, int tid, int c0, int c1)
{
    pf8(sW, W, tid);
    CPCOMMIT();
#pragma unroll 1
    for (int c = 0; c < 32; ++c) {
        CPWAIT0();
        __syncthreads();
        if (c + 1 < 32) { pf8(sW + ((c + 1) & 1) * 2048, W + (c + 1) * 2048, tid); CPCOMMIT(); }
        const float* buf = sW + (c & 1) * 2048;
        const float* Ab = sA + c * 8;
#pragma unroll
        for (int k4 = 0; k4 < 8; k4 += 4) {
            float a[8][4];
#pragma unroll
            for (int r = 0; r < 8; ++r)
                *reinterpret_cast<float4*>(a[r]) =
                    *reinterpret_cast<const float4*>(Ab + r * 256 + k4);
#pragma unroll
            for (int kk = 0; kk < 4; ++kk) {
                const float* wrow = buf + (k4 + kk) * 256;
                ulonglong2 wA = *reinterpret_cast<const ulonglong2*>(wrow + c0);
                ulonglong2 wB = *reinterpret_cast<const ulonglong2*>(wrow + c1);
#pragma unroll
                for (int r = 0; r < 8; ++r) {
                    ull a2 = pk2(a[r][kk], a[r][kk]);
                    fma2(acc[r * 4 + 0], a2, wA.x);
                    fma2(acc[r * 4 + 1], a2, wA.y);
                    fma2(acc[r * 4 + 2], a2, wB.x);
                    fma2(acc[r * 4 + 3], a2, wB.y);
                }
            }
        }
    }
}

// ---------- entity weight staging ----------
__device__ __forceinline__ void load_ent(float* __restrict__ sEnt,
    const float* __restrict__ W, const float* __restrict__ b, int F, int tid)
{
    for (int i = tid; i < F * 256; i += NTHREADS) sEnt[i] = W[i];
    sEnt[F * 256 + tid] = b[tid];
}

// ---------- attention: warp owns 8 rows (two 4-row batches), online softmax ----------
// feats read directly from global (broadcast); q in S1 (in place -> vi).
template<int N, int F>
__device__ __forceinline__ void attend(
    const float* __restrict__ gRow,    // gIn + (row0+r0)*OBS + off
    const float* __restrict__ sEnt,    // W (F x 256) then b (256)
    float* __restrict__ sV,            // S1 + r0*256
    int c0, int c1)
{
    float4 bA = *reinterpret_cast<const float4*>(sEnt + F * 256 + c0);
    float4 bB = *reinterpret_cast<const float4*>(sEnt + F * 256 + c1);
    ull bb0 = pk2(bA.x, bA.y), bb1 = pk2(bA.z, bA.w);
    ull bb2 = pk2(bB.x, bB.y), bb3 = pk2(bB.z, bB.w);

#pragma unroll 1
    for (int half = 0; half < 2; ++half) {
        const float* fR = gRow + half * 4 * OBS;
        float* sVr = sV + half * 4 * 256;

        float q[4][8];
#pragma unroll
        for (int r = 0; r < 4; ++r) {
            float4 qA = *reinterpret_cast<const float4*>(sVr + r * 256 + c0);
            float4 qB = *reinterpret_cast<const float4*>(sVr + r * 256 + c1);
            q[r][0] = qA.x; q[r][1] = qA.y; q[r][2] = qA.z; q[r][3] = qA.w;
            q[r][4] = qB.x; q[r][5] = qB.y; q[r][6] = qB.z; q[r][7] = qB.w;
        }
        float m[4], s[4], v[4][8];
#pragma unroll
        for (int r = 0; r < 4; ++r) {
            m[r] = -3.0e38f; s[r] = 0.0f;
#pragma unroll
            for (int i = 0; i < 8; ++i) v[r][i] = 0.0f;
        }

#pragma unroll 1
        for (int n = 0; n < N; ++n) {
            ull e0[4], e1[4], e2[4], e3[4];
#pragma unroll
            for (int r = 0; r < 4; ++r) { e0[r] = bb0; e1[r] = bb1; e2[r] = bb2; e3[r] = bb3; }
            const float* fp = fR + n * F;
#pragma unroll
            for (int j = 0; j < F; ++j) {
                ulonglong2 wA = *reinterpret_cast<const ulonglong2*>(sEnt + j * 256 + c0);
                ulonglong2 wB = *reinterpret_cast<const ulonglong2*>(sEnt + j * 256 + c1);
#pragma unroll
                for (int r = 0; r < 4; ++r) {
                    float fv = fp[r * OBS + j];          // global broadcast load
                    ull f2 = pk2(fv, fv);
                    fma2(e0[r], f2, wA.x); fma2(e1[r], f2, wA.y);
                    fma2(e2[r], f2, wB.x); fma2(e3[r], f2, wB.y);
                }
            }
#pragma unroll
            for (int r = 0; r < 4; ++r) {
                float ee[8];
                float2 t;
                t = upk2(e0[r]); ee[0] = ftanh(t.x); ee[1] = ftanh(t.y);
                t = upk2(e1[r]); ee[2] = ftanh(t.x); ee[3] = ftanh(t.y);
                t = upk2(e2[r]); ee[4] = ftanh(t.x); ee[5] = ftanh(t.y);
                t = upk2(e3[r]); ee[6] = ftanh(t.x); ee[7] = ftanh(t.y);

                float beta = q[r][0] * ee[0] + q[r][1] * ee[1] + q[r][2] * ee[2] + q[r][3] * ee[3]
                           + q[r][4] * ee[4] + q[r][5] * ee[5] + q[r][6] * ee[6] + q[r][7] * ee[7];
#pragma unroll
                for (int sh = 16; sh > 0; sh >>= 1)
                    beta += __shfl_xor_sync(0xffffffffu, beta, sh);

                float mn = fmaxf(m[r], beta);
                float sc = __expf(m[r] - mn);    // 0 on first entity
                float wt = __expf(beta - mn);
                s[r] = s[r] * sc + wt;
#pragma unroll
                for (int i = 0; i < 8; ++i) v[r][i] = v[r][i] * sc + wt * ee[i];
                m[r] = mn;
            }
        }
#pragma unroll
        for (int r = 0; r < 4; ++r) {
            float inv = __fdividef(1.0f, s[r]);
            *reinterpret_cast<float4*>(sVr + r * 256 + c0) =
                make_float4(v[r][0] * inv, v[r][1] * inv, v[r][2] * inv, v[r][3] * inv);
            *reinterpret_cast<float4*>(sVr + r * 256 + c1) =
                make_float4(v[r][4] * inv, v[r][5] * inv, v[r][6] * inv, v[r][7] * inv);
        }
    }
}

// Shared memory layout (floats):
//  S0   @ 0     : 64*256 = 16384  (emb_self)
//  S1   @ 16384 : 16384           (gi -> q0/vi0 -> q1/vi1 -> q2/vi2)
//  S2   @ 32768 : 16384           (h accumulator -> h)
//  sW   @ 49152 : 4096            (GEMM double buffer 2 x 2048)
//  sEnt @ 53248 : 3584            (current entity group W+b)
// total 56832 floats = 227328 bytes
#define SMEM_FLOATS 56832
#define SMEM_BYTES  (SMEM_FLOATS * 4)

__global__ void __launch_bounds__(NTHREADS, 1)
obs_encoder_kernel(
    const float* __restrict__ gIn,
    const float* __restrict__ W_self,  const float* __restrict__ b_self,
    const float* __restrict__ W_other, const float* __restrict__ b_other,
    const float* __restrict__ W_box,   const float* __restrict__ b_box,
    const float* __restrict__ W_ramp,  const float* __restrict__ b_ramp,
    const float* __restrict__ corr_other, const float* __restrict__ corr_box,
    const float* __restrict__ corr_ramp,
    const float* __restrict__ W_fc, const float* __restrict__ b_fc,
    const float* __restrict__ W_e1, const float* __restrict__ b_e1,
    const float* __restrict__ W_e2, const float* __restrict__ b_e2,
    float* __restrict__ out)
{
    extern __shared__ float sm[];
    float* S0   = sm;
    float* S1   = sm + 16384;
    float* S2   = sm + 32768;
    float* sW   = sm + 49152;
    float* sEnt = sm + 53248;

    const int tid  = threadIdx.x;
    const int lane = tid & 31;
    const int w    = tid >> 5;            // 0..7
    const int r0   = w * 8;               // warp's 8 block-local rows
    const int c0   = lane * 4, c1 = c0 + 128;
    const size_t row0 = (size_t)blockIdx.x * TB;

    const float* gRow = gIn + (row0 + r0) * OBS;

    ull acc[32];

    // ---- P1: emb_self = tanh(self_in @ W_self + b_self), K=10, A from global ----
    acc_bias(acc, b_self, c0, c1);
#pragma unroll
    for (int k = 0; k < 10; ++k) {
        ulonglong2 wA = *reinterpret_cast<const ulonglong2*>(W_self + k * 256 + c0);
        ulonglong2 wB = *reinterpret_cast<const ulonglong2*>(W_self + k * 256 + c1);
#pragma unroll
        for (int r = 0; r < 8; ++r) {
            float av = gRow[r * OBS + k];
            ull a2 = pk2(av, av);
            fma2(acc[r * 4 + 0], a2, wA.x); fma2(acc[r * 4 + 1], a2, wA.y);
            fma2(acc[r * 4 + 2], a2, wB.x); fma2(acc[r * 4 + 3], a2, wB.y);
        }
    }
    epi_tanh(S0 + r0 * 256, c0, c1, acc);
    // gemm256's first internal __syncthreads orders S0 before A-reads

    // ---- G1: gi = tanh(emb @ W_fc + b_fc) -> S1 ----
    acc_bias(acc, b_fc, c0, c1);
    gemm256(acc, S0 + r0 * 256, W_fc, sW, tid, c0, c1);
    epi_tanh(S1 + r0 * 256, c0, c1, acc);

    // ---- G2: h  = gi @ W_e1[0:256] + b_e1 -> S2 (raw) ----
    acc_bias(acc, b_e1, c0, c1);
    gemm256(acc, S1 + r0 * 256, W_e1, sW, tid, c0, c1);
    epi_raw(S2 + r0 * 256, c0, c1, acc);

    // ---- G3: q_other = emb @ corr_other -> S1 ; attend other ; h += vi_o @ W_e1[256:512] ----
    acc_zero(acc);
    gemm256(acc, S0 + r0 * 256, corr_other, sW, tid, c0, c1);
    epi_raw(S1 + r0 * 256, c0, c1, acc);

    load_ent(sEnt, W_other, b_other, 10, tid);
    __syncthreads();
    attend<15, 10>(gRow + 10, sEnt, S1 + r0 * 256, c0, c1);

    acc_zero(acc);
    gemm256(acc, S1 + r0 * 256, W_e1 + 65536, sW, tid, c0, c1);
    epi_add(S2 + r0 * 256, c0, c1, acc);

    // ---- G4: q_box ; attend box ; h += vi_b @ W_e1[512:768] ----
    acc_zero(acc);
    gemm256(acc, S0 + r0 * 256, corr_box, sW, tid, c0, c1);
    epi_raw(S1 + r0 * 256, c0, c1, acc);

    load_ent(sEnt, W_box, b_box, 13, tid);
    __syncthreads();
    attend<16, 13>(gRow + 160, sEnt, S1 + r0 * 256, c0, c1);

    acc_zero(acc);
    gemm256(acc, S1 + r0 * 256, W_e1 + 131072, sW, tid, c0, c1);
    epi_add(S2 + r0 * 256, c0, c1, acc);

    // ---- G5: q_ramp ; attend ramp ; h = tanh(h + vi_r @ W_e1[768:1024]) ----
    acc_zero(acc);
    gemm256(acc, S0 + r0 * 256, corr_ramp, sW, tid, c0, c1);
    epi_raw(S1 + r0 * 256, c0, c1, acc);

    load_ent(sEnt, W_ramp, b_ramp, 12, tid);
    __syncthreads();
    attend<8, 12>(gRow + 368, sEnt, S1 + r0 * 256, c0, c1);

    acc_zero(acc);
    gemm256(acc, S1 + r0 * 256, W_e1 + 196608, sW, tid, c0, c1);
    epi_add_tanh(S2 + r0 * 256, c0, c1, acc);

    // ---- G6: out = tanh(h @ W_e2 + b_e2) -> global (coalesced float4) ----
    acc_bias(acc, b_e2, c0, c1);
    gemm256(acc, S2 + r0 * 256, W_e2, sW, tid, c0, c1);
    {
        float* gdst = out + (row0 + r0) * 256;
#pragma unroll
        for (int r = 0; r < 8; ++r) {
            float2 t0 = upk2(acc[r * 4 + 0]), t1 = upk2(acc[r * 4 + 1]);
            float2 t2 = upk2(acc[r * 4 + 2]), t3 = upk2(acc[r * 4 + 3]);
            *reinterpret_cast<float4*>(gdst + r * 256 + c0) =
                make_float4(ftanh(t0.x), ftanh(t0.y), ftanh(t1.x), ftanh(t1.y));
            *reinterpret_cast<float4*>(gdst + r * 256 + c1) =
                make_float4(ftanh(t2.x), ftanh(t2.y), ftanh(t3.x), ftanh(t3.y));
        }
    }
}

extern "C" void kernel_launch(void* const* d_in, const int* in_sizes, int n_in,
                              void* d_out, int out_size) {
    const float* inputs     = (const float*)d_in[0];
    const float* W_self     = (const float*)d_in[1];
    const float* b_self     = (const float*)d_in[2];
    const float* W_other    = (const float*)d_in[3];
    const float* b_other    = (const float*)d_in[4];
    const float* W_box      = (const float*)d_in[5];
    const float* b_box      = (const float*)d_in[6];
    const float* W_ramp     = (const float*)d_in[7];
    const float* b_ramp     = (const float*)d_in[8];
    const float* corr_other = (const float*)d_in[9];
    const float* corr_box   = (const float*)d_in[10];
    const float* corr_ramp  = (const float*)d_in[11];
    const float* W_fc       = (const float*)d_in[12];
    const float* b_fc       = (const float*)d_in[13];
    const float* W_e1       = (const float*)d_in[14];
    const float* b_e1       = (const float*)d_in[15];
    const float* W_e2       = (const float*)d_in[16];
    const float* b_e2       = (const float*)d_in[17];
    float* out = (float*)d_out;

    const int B = in_sizes[0] / OBS;       // 32768
    const int nblocks = B / TB;            // 512

    cudaFuncSetAttribute(obs_encoder_kernel,
                         cudaFuncAttributeMaxDynamicSharedMemorySize, SMEM_BYTES);

    obs_encoder_kernel<<<nblocks, NTHREADS, SMEM_BYTES>>>(
        inputs, W_self, b_self, W_other, b_other, W_box, b_box, W_ramp, b_ramp,
        corr_other, corr_box, corr_ramp, W_fc, b_fc, W_e1, b_e1, W_e2, b_e2, out);
}